// round 13
// baseline (speedup 1.0000x reference)
#include <cuda_runtime.h>
#include <cuda_fp16.h>
#include <cstdint>

// ============================================================================
// out[2048,4096] = x[2048,4096] * W[4096,4096]^T
//   W = dequant_int4(base_packed, scales) + alpha * scatter(COO fp16)
// fp16 operands, fp32 accum via mma.sync.m16n8k16 (legacy-HMMA ceiling
// established R5-R10; GEMM frozen at R7 config, ~206us).
// Pipeline: 1) dequant_W (bit-trick, ALU-light)  2) combo: scatter via
// red.global.f16 || x->fp16 convert  3) gemm.
// ============================================================================

#define O_FEAT 4096
#define I_FEAT 4096
#define M_ROWS 2048

__device__ __align__(256) __half g_A16[M_ROWS * I_FEAT];
__device__ __align__(256) __half g_W16[O_FEAT * I_FEAT];

__device__ __forceinline__ uint32_t smem_u32(const void* p) {
    uint32_t a;
    asm("{ .reg .u64 t; cvta.to.shared.u64 t, %1; cvt.u32.u64 %0, t; }"
        : "=r"(a) : "l"(p));
    return a;
}

// packed int32-canonicalized iff leading 4 words all in [0,255]
__device__ __forceinline__ bool packed_is_int32(const void* bp) {
    int4 w = __ldg(reinterpret_cast<const int4*>(bp));
    return ((unsigned)w.x <= 255u) && ((unsigned)w.y <= 255u) &&
           ((unsigned)w.z <= 255u) && ((unsigned)w.w <= 255u);
}

// vals float32 iff leading 4 f32 are finite with max|v| in (1e-8, 1)
__device__ __forceinline__ bool vals_is_f32(const void* vals) {
    float4 v = __ldg(reinterpret_cast<const float4*>(vals));
    float m = fmaxf(fmaxf(fabsf(v.x), fabsf(v.y)), fmaxf(fabsf(v.z), fabsf(v.w)));
    return isfinite(m) && m > 1e-8f && m < 1.0f;
}

__device__ __forceinline__ float read_alpha(const float* alphap) {
    float a = 1.0f;
    if (alphap) {
        float f = __ldg(alphap);
        if (isfinite(f) && fabsf(f) > 1e-30f && fabsf(f) < 1e30f) {
            a = f;  // float32 alpha
        } else {
            double d = __ldg(reinterpret_cast<const double*>(alphap));
            a = (float)d;  // float64 alpha
        }
    }
    return a;
}

// ---------------------------------------------------------------------------
// 1) dequant W — bit-trick: prmt + fp16 exponent-bias magic.
//    0x6400|q encodes (1024+q); (v - 1032) * s == (q - 8) * s.
// ---------------------------------------------------------------------------
__global__ void dequant_kernel(const void* __restrict__ bp,
                               const float* __restrict__ scales) {
    const int idx = blockIdx.x * blockDim.x + threadIdx.x;
    if (idx >= O_FEAT * I_FEAT / 8) return;
    const bool pk32 = packed_is_int32(bp);
    int o = idx >> 9;   // 512 u32-groups per output row
    int j = idx & 511;
    unsigned int p;
    if (pk32) {
        const int4 pi = reinterpret_cast<const int4*>(bp)[idx];
        p = (unsigned)(pi.x & 0xFF) | ((unsigned)(pi.y & 0xFF) << 8) |
            ((unsigned)(pi.z & 0xFF) << 16) | ((unsigned)(pi.w & 0xFF) << 24);
    } else {
        p = reinterpret_cast<const unsigned int*>(bp)[idx];
    }
    const unsigned lo = p & 0x0F0F0F0Fu;         // low nibbles (even cols)
    const unsigned hi = (p >> 4) & 0x0F0F0F0Fu;  // high nibbles (odd cols)
    const unsigned c1032 = 0x64086408u;          // half2(1032, 1032)
    const __half2 h1032 = *reinterpret_cast<const __half2*>(&c1032);
    const __half2 s2 = __float2half2_rn(scales[o]);

    __align__(16) __half2 h[4];
#pragma unroll
    for (int b = 0; b < 4; ++b) {
        unsigned sel = 0x0400u + (unsigned)b * 0x0101u;  // 0x0400,0x0501,...
        unsigned v = __byte_perm(lo, hi, sel);
        v = (v & 0x000F000Fu) | 0x64006400u;  // half2(1024+lo_b, 1024+hi_b)
        __half2 hv = *reinterpret_cast<const __half2*>(&v);
        h[b] = __hmul2(__hsub2(hv, h1032), s2);
    }
    reinterpret_cast<uint4*>(g_W16 + (size_t)o * I_FEAT + (size_t)j * 8)[0] =
        *reinterpret_cast<const uint4*>(h);
}

// ---------------------------------------------------------------------------
// 2) combo: scatter via red.global.add.noftz.f16 (block range [0, nScB))
//    || x->fp16 convert (rest). Disjoint outputs (W16 vs A16).
// ---------------------------------------------------------------------------
__global__ void combo_kernel(const float* __restrict__ x,
                             const void* __restrict__ vals,
                             const int* __restrict__ rows,
                             const int* __restrict__ cols,
                             const float* __restrict__ alphap, int nnz,
                             int nScB) {
    if ((int)blockIdx.x < nScB) {
        int i = blockIdx.x * blockDim.x + threadIdx.x;
        if (i >= nnz) return;
        float a = read_alpha(alphap);
        float v;
        if (vals_is_f32(vals)) v = reinterpret_cast<const float*>(vals)[i];
        else v = __half2float(reinterpret_cast<const __half*>(vals)[i]);
        __half hv = __float2half(v * a);
        unsigned short bits = *reinterpret_cast<unsigned short*>(&hv);
        __half* dst = g_W16 + (size_t)rows[i] * I_FEAT + cols[i];
        asm volatile("red.global.add.noftz.f16 [%0], %1;"
                     :: "l"(dst), "h"(bits) : "memory");
    } else {
        int idx = (blockIdx.x - nScB) * blockDim.x + threadIdx.x;
        if (idx >= M_ROWS * I_FEAT / 8) return;
        const float4* xv = reinterpret_cast<const float4*>(x) + (size_t)idx * 2;
        float4 a = xv[0], b = xv[1];
        __align__(16) __half2 h[4];
        h[0] = __floats2half2_rn(a.x, a.y);
        h[1] = __floats2half2_rn(a.z, a.w);
        h[2] = __floats2half2_rn(b.x, b.y);
        h[3] = __floats2half2_rn(b.z, b.w);
        reinterpret_cast<uint4*>(g_A16)[idx] = *reinterpret_cast<const uint4*>(h);
    }
}

// ---------------------------------------------------------------------------
// GEMM (frozen R7 config): CTA tile 128x128, BK=64, 3-stage cp.async,
// 4 warps (2x2, warp tile 64x64), 2 CTAs/SM, ldmatrix.x4, f32 accum.
// ---------------------------------------------------------------------------
#define BM 128
#define BN 128
#define BK 64
#define STAGES 3
#define KCHUNKS (I_FEAT / BK)              // 64
#define A_BYTES (BM * 128)                 // 16384
#define B_BYTES (BN * 128)                 // 16384
#define STAGE_BYTES (A_BYTES + B_BYTES)    // 32768
#define SMEM_TOTAL (STAGES * STAGE_BYTES)  // 98304
#define NTHREADS 128

__device__ __forceinline__ void ldsm_x4(uint32_t* r, uint32_t addr) {
    asm volatile("ldmatrix.sync.aligned.m8n8.x4.shared.b16 {%0,%1,%2,%3}, [%4];"
                 : "=r"(r[0]), "=r"(r[1]), "=r"(r[2]), "=r"(r[3]) : "r"(addr));
}

__device__ __forceinline__ void mma16816(float* c, const uint32_t* a,
                                         uint32_t b0, uint32_t b1) {
    asm volatile(
        "mma.sync.aligned.m16n8k16.row.col.f32.f16.f16.f32 "
        "{%0,%1,%2,%3}, {%4,%5,%6,%7}, {%8,%9}, {%0,%1,%2,%3};"
        : "+f"(c[0]), "+f"(c[1]), "+f"(c[2]), "+f"(c[3])
        : "r"(a[0]), "r"(a[1]), "r"(a[2]), "r"(a[3]), "r"(b0), "r"(b1));
}

__global__ void __launch_bounds__(NTHREADS, 2)
gemm_kernel(float* __restrict__ out) {
    extern __shared__ char smem[];
    const uint32_t sbase = smem_u32(smem);
    const int tid = threadIdx.x;
    const int wid = tid >> 5;
    const int lid = tid & 31;
    const int bx = blockIdx.x;   // N tile (0..31)
    const int by = blockIdx.y;   // M tile (0..15)

    const int wm = wid >> 1;     // 0..1  (M: 64 rows)
    const int wn = wid & 1;      // 0..1  (N: 64 cols)

    const __half* gA = g_A16 + (size_t)by * BM * I_FEAT;
    const __half* gB = g_W16 + (size_t)bx * BN * I_FEAT;

    const int rlocal = (lid & 7) + ((lid >> 3) & 1) * 8;  // 0..15
    const int csel = lid >> 4;                            // 0/1

    float acc[4][8][4];
#pragma unroll
    for (int a = 0; a < 4; ++a)
#pragma unroll
        for (int b = 0; b < 8; ++b)
#pragma unroll
            for (int r = 0; r < 4; ++r) acc[a][b][r] = 0.0f;

#define LOAD_STAGE(s, ch)                                                      \
    do {                                                                       \
        uint32_t aB_ = sbase + (uint32_t)(s) * STAGE_BYTES;                    \
        uint32_t bB_ = aB_ + A_BYTES;                                          \
        _Pragma("unroll")                                                      \
        for (int i_ = 0; i_ < 8; ++i_) {                                       \
            int id_ = tid + i_ * NTHREADS;                                     \
            int row_ = id_ >> 3, c_ = id_ & 7;                                 \
            uint32_t sw_ = (uint32_t)(c_ ^ (row_ & 7)) << 4;                   \
            uint32_t da_ = aB_ + (uint32_t)row_ * 128u + sw_;                  \
            const __half* sa_ = gA + (size_t)row_ * I_FEAT + (ch) * BK + c_ * 8; \
            asm volatile("cp.async.cg.shared.global [%0], [%1], 16;"          \
                         :: "r"(da_), "l"(sa_) : "memory");                    \
            uint32_t db_ = bB_ + (uint32_t)row_ * 128u + sw_;                  \
            const __half* sb_ = gB + (size_t)row_ * I_FEAT + (ch) * BK + c_ * 8; \
            asm volatile("cp.async.cg.shared.global [%0], [%1], 16;"          \
                         :: "r"(db_), "l"(sb_) : "memory");                    \
        }                                                                      \
        asm volatile("cp.async.commit_group;" ::: "memory");                   \
    } while (0)

    LOAD_STAGE(0, 0);
    LOAD_STAGE(1, 1);

    int s = 0;
    for (int ch = 0; ch < KCHUNKS; ++ch) {
        if (ch == KCHUNKS - 1) {
            asm volatile("cp.async.wait_group 0;" ::: "memory");
        } else {
            asm volatile("cp.async.wait_group 1;" ::: "memory");
        }
        __syncthreads();

        if (ch + 2 < KCHUNKS) {
            int s2 = s + 2;
            if (s2 >= STAGES) s2 -= STAGES;
            LOAD_STAGE(s2, ch + 2);
        }

        const uint32_t aB = sbase + (uint32_t)s * STAGE_BYTES;
        const uint32_t bB = aB + A_BYTES;

#pragma unroll
        for (int ks = 0; ks < 4; ++ks) {
            const int kc = ks * 2 + csel;
            uint32_t rb[4][4];
#pragma unroll
            for (int nt = 0; nt < 4; ++nt) {
                int row = wn * 64 + nt * 16 + rlocal;
                uint32_t addr = bB + (uint32_t)row * 128u +
                                ((uint32_t)(kc ^ (row & 7)) << 4);
                ldsm_x4(rb[nt], addr);
            }
#pragma unroll
            for (int mt = 0; mt < 4; ++mt) {
                int row = wm * 64 + mt * 16 + rlocal;
                uint32_t addr = aB + (uint32_t)row * 128u +
                                ((uint32_t)(kc ^ (row & 7)) << 4);
                uint32_t ra[4];
                ldsm_x4(ra, addr);
#pragma unroll
                for (int nt = 0; nt < 4; ++nt) {
                    mma16816(acc[mt][2 * nt],     ra, rb[nt][0], rb[nt][2]);
                    mma16816(acc[mt][2 * nt + 1], ra, rb[nt][1], rb[nt][3]);
                }
            }
        }

        if (++s == STAGES) s = 0;
    }

    const int r0 = lid >> 2;
    const int c0 = (lid & 3) * 2;
#pragma unroll
    for (int mt = 0; mt < 4; ++mt) {
        int m0 = by * BM + wm * 64 + mt * 16 + r0;
#pragma unroll
        for (int nf = 0; nf < 8; ++nf) {
            int nt = nf >> 1, hi = nf & 1;
            int n0 = bx * BN + wn * 64 + nt * 16 + hi * 8 + c0;
            float2 v0 = make_float2(acc[mt][nf][0], acc[mt][nf][1]);
            float2 v1 = make_float2(acc[mt][nf][2], acc[mt][nf][3]);
            *reinterpret_cast<float2*>(out + (size_t)m0 * O_FEAT + n0) = v0;
            *reinterpret_cast<float2*>(out + (size_t)(m0 + 8) * O_FEAT + n0) = v1;
        }
    }
}

// ---------------------------------------------------------------------------
// kernel_launch — dequant, combo(scatter || xconvert), gemm
// ---------------------------------------------------------------------------
extern "C" void kernel_launch(void* const* d_in, const int* in_sizes, int n_in,
                              void* d_out, int out_size) {
    const float* x      = (const float*)d_in[0];
    const void*  bp     = d_in[1];
    const float* scales = (const float*)d_in[2];
    const void*  vals   = d_in[3];
    const int*   rows   = (const int*)d_in[4];
    const int*   cols   = (const int*)d_in[5];
    const float* alphap = (n_in > 6) ? (const float*)d_in[6] : nullptr;
    const int nnz = in_sizes[3];

    const int nScB = (nnz + 255) / 256;                  // scatter blocks
    const int nXB  = (M_ROWS * I_FEAT / 8 + 255) / 256;  // xconvert blocks

    dequant_kernel<<<(O_FEAT * I_FEAT / 8 + 255) / 256, 256>>>(bp, scales);
    combo_kernel<<<nScB + nXB, 256>>>(x, vals, rows, cols, alphap, nnz, nScB);

    cudaFuncSetAttribute(gemm_kernel,
                         cudaFuncAttributeMaxDynamicSharedMemorySize, SMEM_TOTAL);
    gemm_kernel<<<dim3(O_FEAT / BN, M_ROWS / BM, 1), NTHREADS, SMEM_TOTAL>>>(
        (float*)d_out);
}

// round 14
// speedup vs baseline: 1.5353x; 1.5353x over previous
#include <cuda_runtime.h>
#include <cuda_fp16.h>
#include <cstdint>

// ============================================================================
// out[2048,4096] = x[2048,4096] * W[4096,4096]^T
//   W = dequant_int4(base_packed, scales) + alpha * scatter(COO fp16)
// fp16 operands, fp32 accum via mma.sync.m16n8k16 (legacy-HMMA ceiling
// established R5-R10; GEMM frozen at R7 config, ~206us).
// Pipeline (R12 structure): 1) dequant_W (exact I2F — fastest measured)
// 2) combo: scatter via native half2 atomics || x->fp16 convert  3) gemm.
// ============================================================================

#define O_FEAT 4096
#define I_FEAT 4096
#define M_ROWS 2048

__device__ __align__(256) __half g_A16[M_ROWS * I_FEAT];
__device__ __align__(256) __half g_W16[O_FEAT * I_FEAT];

__device__ __forceinline__ uint32_t smem_u32(const void* p) {
    uint32_t a;
    asm("{ .reg .u64 t; cvta.to.shared.u64 t, %1; cvt.u32.u64 %0, t; }"
        : "=r"(a) : "l"(p));
    return a;
}

// packed int32-canonicalized iff leading 4 words all in [0,255]
__device__ __forceinline__ bool packed_is_int32(const void* bp) {
    int4 w = __ldg(reinterpret_cast<const int4*>(bp));
    return ((unsigned)w.x <= 255u) && ((unsigned)w.y <= 255u) &&
           ((unsigned)w.z <= 255u) && ((unsigned)w.w <= 255u);
}

// vals float32 iff leading 4 f32 are finite with max|v| in (1e-8, 1)
__device__ __forceinline__ bool vals_is_f32(const void* vals) {
    float4 v = __ldg(reinterpret_cast<const float4*>(vals));
    float m = fmaxf(fmaxf(fabsf(v.x), fabsf(v.y)), fmaxf(fabsf(v.z), fabsf(v.w)));
    return isfinite(m) && m > 1e-8f && m < 1.0f;
}

__device__ __forceinline__ float read_alpha(const float* alphap) {
    float a = 1.0f;
    if (alphap) {
        float f = __ldg(alphap);
        if (isfinite(f) && fabsf(f) > 1e-30f && fabsf(f) < 1e30f) {
            a = f;  // float32 alpha
        } else {
            double d = __ldg(reinterpret_cast<const double*>(alphap));
            a = (float)d;  // float64 alpha
        }
    }
    return a;
}

// ---------------------------------------------------------------------------
// 1) dequant W (exact I2F version — fastest measured at 14.8us)
// ---------------------------------------------------------------------------
__global__ void dequant_kernel(const void* __restrict__ bp,
                               const float* __restrict__ scales) {
    const int idx = blockIdx.x * blockDim.x + threadIdx.x;
    if (idx >= O_FEAT * I_FEAT / 8) return;
    const bool pk32 = packed_is_int32(bp);
    int o = idx >> 9;   // 512 u32-groups per output row
    int j = idx & 511;
    unsigned int p;
    if (pk32) {
        const int4 pi = reinterpret_cast<const int4*>(bp)[idx];
        p = (unsigned)(pi.x & 0xFF) | ((unsigned)(pi.y & 0xFF) << 8) |
            ((unsigned)(pi.z & 0xFF) << 16) | ((unsigned)(pi.w & 0xFF) << 24);
    } else {
        p = reinterpret_cast<const unsigned int*>(bp)[idx];
    }
    float s = scales[o];
    __align__(16) __half2 h[4];
#pragma unroll
    for (int b = 0; b < 4; ++b) {
        int q = (p >> (8 * b)) & 0xFF;
        float lo = (float)((q & 0xF) - 8) * s;   // low nibble -> even col
        float hi = (float)((q >> 4) - 8) * s;    // high nibble -> odd col
        h[b] = __floats2half2_rn(lo, hi);
    }
    reinterpret_cast<uint4*>(g_W16 + (size_t)o * I_FEAT + (size_t)j * 8)[0] =
        *reinterpret_cast<const uint4*>(h);
}

// ---------------------------------------------------------------------------
// 2) combo: scatter (block range [0, nScB)) || x->fp16 convert (rest).
//    Scatter uses NATIVE half2 atomics at the containing aligned 32-bit word:
//    (v, +0) or (+0, v) by column parity — adding +0 to the partner half is
//    value-preserving for the GEMM.
// ---------------------------------------------------------------------------
__global__ void combo_kernel(const float* __restrict__ x,
                             const void* __restrict__ vals,
                             const int* __restrict__ rows,
                             const int* __restrict__ cols,
                             const float* __restrict__ alphap, int nnz,
                             int nScB) {
    if ((int)blockIdx.x < nScB) {
        int i = blockIdx.x * blockDim.x + threadIdx.x;
        if (i >= nnz) return;
        float a = read_alpha(alphap);
        float v;
        if (vals_is_f32(vals)) v = reinterpret_cast<const float*>(vals)[i];
        else v = __half2float(reinterpret_cast<const __half*>(vals)[i]);
        __half hv = __float2half(v * a);
        int col = cols[i];
        __half2 up = (col & 1) ? __halves2half2(__ushort_as_half(0), hv)
                               : __halves2half2(hv, __ushort_as_half(0));
        __half2* dst = reinterpret_cast<__half2*>(
            g_W16 + (size_t)rows[i] * I_FEAT + (col & ~1));
        atomicAdd(dst, up);
    } else {
        int idx = (blockIdx.x - nScB) * blockDim.x + threadIdx.x;
        if (idx >= M_ROWS * I_FEAT / 8) return;
        const float4* xv = reinterpret_cast<const float4*>(x) + (size_t)idx * 2;
        float4 a = xv[0], b = xv[1];
        __align__(16) __half2 h[4];
        h[0] = __floats2half2_rn(a.x, a.y);
        h[1] = __floats2half2_rn(a.z, a.w);
        h[2] = __floats2half2_rn(b.x, b.y);
        h[3] = __floats2half2_rn(b.z, b.w);
        reinterpret_cast<uint4*>(g_A16)[idx] = *reinterpret_cast<const uint4*>(h);
    }
}

// ---------------------------------------------------------------------------
// GEMM (frozen R7 config): CTA tile 128x128, BK=64, 3-stage cp.async,
// 4 warps (2x2, warp tile 64x64), 2 CTAs/SM, ldmatrix.x4, f32 accum.
// ---------------------------------------------------------------------------
#define BM 128
#define BN 128
#define BK 64
#define STAGES 3
#define KCHUNKS (I_FEAT / BK)              // 64
#define A_BYTES (BM * 128)                 // 16384
#define B_BYTES (BN * 128)                 // 16384
#define STAGE_BYTES (A_BYTES + B_BYTES)    // 32768
#define SMEM_TOTAL (STAGES * STAGE_BYTES)  // 98304
#define NTHREADS 128

__device__ __forceinline__ void ldsm_x4(uint32_t* r, uint32_t addr) {
    asm volatile("ldmatrix.sync.aligned.m8n8.x4.shared.b16 {%0,%1,%2,%3}, [%4];"
                 : "=r"(r[0]), "=r"(r[1]), "=r"(r[2]), "=r"(r[3]) : "r"(addr));
}

__device__ __forceinline__ void mma16816(float* c, const uint32_t* a,
                                         uint32_t b0, uint32_t b1) {
    asm volatile(
        "mma.sync.aligned.m16n8k16.row.col.f32.f16.f16.f32 "
        "{%0,%1,%2,%3}, {%4,%5,%6,%7}, {%8,%9}, {%0,%1,%2,%3};"
        : "+f"(c[0]), "+f"(c[1]), "+f"(c[2]), "+f"(c[3])
        : "r"(a[0]), "r"(a[1]), "r"(a[2]), "r"(a[3]), "r"(b0), "r"(b1));
}

__global__ void __launch_bounds__(NTHREADS, 2)
gemm_kernel(float* __restrict__ out) {
    extern __shared__ char smem[];
    const uint32_t sbase = smem_u32(smem);
    const int tid = threadIdx.x;
    const int wid = tid >> 5;
    const int lid = tid & 31;
    const int bx = blockIdx.x;   // N tile (0..31)
    const int by = blockIdx.y;   // M tile (0..15)

    const int wm = wid >> 1;     // 0..1  (M: 64 rows)
    const int wn = wid & 1;      // 0..1  (N: 64 cols)

    const __half* gA = g_A16 + (size_t)by * BM * I_FEAT;
    const __half* gB = g_W16 + (size_t)bx * BN * I_FEAT;

    const int rlocal = (lid & 7) + ((lid >> 3) & 1) * 8;  // 0..15
    const int csel = lid >> 4;                            // 0/1

    float acc[4][8][4];
#pragma unroll
    for (int a = 0; a < 4; ++a)
#pragma unroll
        for (int b = 0; b < 8; ++b)
#pragma unroll
            for (int r = 0; r < 4; ++r) acc[a][b][r] = 0.0f;

#define LOAD_STAGE(s, ch)                                                      \
    do {                                                                       \
        uint32_t aB_ = sbase + (uint32_t)(s) * STAGE_BYTES;                    \
        uint32_t bB_ = aB_ + A_BYTES;                                          \
        _Pragma("unroll")                                                      \
        for (int i_ = 0; i_ < 8; ++i_) {                                       \
            int id_ = tid + i_ * NTHREADS;                                     \
            int row_ = id_ >> 3, c_ = id_ & 7;                                 \
            uint32_t sw_ = (uint32_t)(c_ ^ (row_ & 7)) << 4;                   \
            uint32_t da_ = aB_ + (uint32_t)row_ * 128u + sw_;                  \
            const __half* sa_ = gA + (size_t)row_ * I_FEAT + (ch) * BK + c_ * 8; \
            asm volatile("cp.async.cg.shared.global [%0], [%1], 16;"          \
                         :: "r"(da_), "l"(sa_) : "memory");                    \
            uint32_t db_ = bB_ + (uint32_t)row_ * 128u + sw_;                  \
            const __half* sb_ = gB + (size_t)row_ * I_FEAT + (ch) * BK + c_ * 8; \
            asm volatile("cp.async.cg.shared.global [%0], [%1], 16;"          \
                         :: "r"(db_), "l"(sb_) : "memory");                    \
        }                                                                      \
        asm volatile("cp.async.commit_group;" ::: "memory");                   \
    } while (0)

    LOAD_STAGE(0, 0);
    LOAD_STAGE(1, 1);

    int s = 0;
    for (int ch = 0; ch < KCHUNKS; ++ch) {
        if (ch == KCHUNKS - 1) {
            asm volatile("cp.async.wait_group 0;" ::: "memory");
        } else {
            asm volatile("cp.async.wait_group 1;" ::: "memory");
        }
        __syncthreads();

        if (ch + 2 < KCHUNKS) {
            int s2 = s + 2;
            if (s2 >= STAGES) s2 -= STAGES;
            LOAD_STAGE(s2, ch + 2);
        }

        const uint32_t aB = sbase + (uint32_t)s * STAGE_BYTES;
        const uint32_t bB = aB + A_BYTES;

#pragma unroll
        for (int ks = 0; ks < 4; ++ks) {
            const int kc = ks * 2 + csel;
            uint32_t rb[4][4];
#pragma unroll
            for (int nt = 0; nt < 4; ++nt) {
                int row = wn * 64 + nt * 16 + rlocal;
                uint32_t addr = bB + (uint32_t)row * 128u +
                                ((uint32_t)(kc ^ (row & 7)) << 4);
                ldsm_x4(rb[nt], addr);
            }
#pragma unroll
            for (int mt = 0; mt < 4; ++mt) {
                int row = wm * 64 + mt * 16 + rlocal;
                uint32_t addr = aB + (uint32_t)row * 128u +
                                ((uint32_t)(kc ^ (row & 7)) << 4);
                uint32_t ra[4];
                ldsm_x4(ra, addr);
#pragma unroll
                for (int nt = 0; nt < 4; ++nt) {
                    mma16816(acc[mt][2 * nt],     ra, rb[nt][0], rb[nt][2]);
                    mma16816(acc[mt][2 * nt + 1], ra, rb[nt][1], rb[nt][3]);
                }
            }
        }

        if (++s == STAGES) s = 0;
    }

    const int r0 = lid >> 2;
    const int c0 = (lid & 3) * 2;
#pragma unroll
    for (int mt = 0; mt < 4; ++mt) {
        int m0 = by * BM + wm * 64 + mt * 16 + r0;
#pragma unroll
        for (int nf = 0; nf < 8; ++nf) {
            int nt = nf >> 1, hi = nf & 1;
            int n0 = bx * BN + wn * 64 + nt * 16 + hi * 8 + c0;
            float2 v0 = make_float2(acc[mt][nf][0], acc[mt][nf][1]);
            float2 v1 = make_float2(acc[mt][nf][2], acc[mt][nf][3]);
            *reinterpret_cast<float2*>(out + (size_t)m0 * O_FEAT + n0) = v0;
            *reinterpret_cast<float2*>(out + (size_t)(m0 + 8) * O_FEAT + n0) = v1;
        }
    }
}

// ---------------------------------------------------------------------------
// kernel_launch — dequant, combo(scatter || xconvert), gemm
// ---------------------------------------------------------------------------
extern "C" void kernel_launch(void* const* d_in, const int* in_sizes, int n_in,
                              void* d_out, int out_size) {
    const float* x      = (const float*)d_in[0];
    const void*  bp     = d_in[1];
    const float* scales = (const float*)d_in[2];
    const void*  vals   = d_in[3];
    const int*   rows   = (const int*)d_in[4];
    const int*   cols   = (const int*)d_in[5];
    const float* alphap = (n_in > 6) ? (const float*)d_in[6] : nullptr;
    const int nnz = in_sizes[3];

    const int nScB = (nnz + 255) / 256;                  // scatter blocks
    const int nXB  = (M_ROWS * I_FEAT / 8 + 255) / 256;  // xconvert blocks

    dequant_kernel<<<(O_FEAT * I_FEAT / 8 + 255) / 256, 256>>>(bp, scales);
    combo_kernel<<<nScB + nXB, 256>>>(x, vals, rows, cols, alphap, nnz, nScB);

    cudaFuncSetAttribute(gemm_kernel,
                         cudaFuncAttributeMaxDynamicSharedMemorySize, SMEM_TOTAL);
    gemm_kernel<<<dim3(O_FEAT / BN, M_ROWS / BM, 1), NTHREADS, SMEM_TOTAL>>>(
        (float*)d_out);
}

// round 15
// speedup vs baseline: 1.5395x; 1.0027x over previous
#include <cuda_runtime.h>
#include <cuda_fp16.h>
#include <cstdint>

// ============================================================================
// out[2048,4096] = x[2048,4096] * W[4096,4096]^T
//   W = dequant_int4(base_packed, scales) + alpha * scatter(COO fp16)
// fp16 operands, fp32 accum via mma.sync.m16n8k16 (legacy-HMMA rate plateau
// established R5-R10; GEMM frozen at R7 config, ~206us).
// Pipeline: 1) dequant_W (PRMT word assembly + exact I2F)
//           2) combo launched with PDL: xconvert blocks overlap dequant,
//              scatter blocks griddepsync then half2-atomic into W
//           3) gemm
// ============================================================================

#define O_FEAT 4096
#define I_FEAT 4096
#define M_ROWS 2048

__device__ __align__(256) __half g_A16[M_ROWS * I_FEAT];
__device__ __align__(256) __half g_W16[O_FEAT * I_FEAT];

__device__ __forceinline__ uint32_t smem_u32(const void* p) {
    uint32_t a;
    asm("{ .reg .u64 t; cvta.to.shared.u64 t, %1; cvt.u32.u64 %0, t; }"
        : "=r"(a) : "l"(p));
    return a;
}

// packed int32-canonicalized iff leading 4 words all in [0,255]
__device__ __forceinline__ bool packed_is_int32(const void* bp) {
    int4 w = __ldg(reinterpret_cast<const int4*>(bp));
    return ((unsigned)w.x <= 255u) && ((unsigned)w.y <= 255u) &&
           ((unsigned)w.z <= 255u) && ((unsigned)w.w <= 255u);
}

// vals float32 iff leading 4 f32 are finite with max|v| in (1e-8, 1)
__device__ __forceinline__ bool vals_is_f32(const void* vals) {
    float4 v = __ldg(reinterpret_cast<const float4*>(vals));
    float m = fmaxf(fmaxf(fabsf(v.x), fabsf(v.y)), fmaxf(fabsf(v.z), fabsf(v.w)));
    return isfinite(m) && m > 1e-8f && m < 1.0f;
}

__device__ __forceinline__ float read_alpha(const float* alphap) {
    float a = 1.0f;
    if (alphap) {
        float f = __ldg(alphap);
        if (isfinite(f) && fabsf(f) > 1e-30f && fabsf(f) < 1e30f) {
            a = f;  // float32 alpha
        } else {
            double d = __ldg(reinterpret_cast<const double*>(alphap));
            a = (float)d;  // float64 alpha
        }
    }
    return a;
}

// ---------------------------------------------------------------------------
// 1) dequant W — PRMT gathers byte0 of 4 int32 words; exact I2F dequant.
// Grid exactly covers the domain (no early returns), trigger fires at end.
// ---------------------------------------------------------------------------
__global__ void dequant_kernel(const void* __restrict__ bp,
                               const float* __restrict__ scales) {
    const int idx = blockIdx.x * blockDim.x + threadIdx.x;  // 0..2M-1 exact
    const bool pk32 = packed_is_int32(bp);
    int o = idx >> 9;   // 512 u32-groups per output row
    int j = idx & 511;
    unsigned int p;
    if (pk32) {
        const int4 pi = reinterpret_cast<const int4*>(bp)[idx];
        unsigned t0 = __byte_perm((unsigned)pi.x, (unsigned)pi.y, 0x0040u);
        unsigned t1 = __byte_perm((unsigned)pi.z, (unsigned)pi.w, 0x0040u);
        p = __byte_perm(t0, t1, 0x5410u);  // [x.b0, y.b0, z.b0, w.b0]
    } else {
        p = reinterpret_cast<const unsigned int*>(bp)[idx];
    }
    float s = scales[o];
    __align__(16) __half2 h[4];
#pragma unroll
    for (int b = 0; b < 4; ++b) {
        int q = (p >> (8 * b)) & 0xFF;
        float lo = (float)((q & 0xF) - 8) * s;   // low nibble -> even col
        float hi = (float)((q >> 4) - 8) * s;    // high nibble -> odd col
        h[b] = __floats2half2_rn(lo, hi);
    }
    reinterpret_cast<uint4*>(g_W16 + (size_t)o * I_FEAT + (size_t)j * 8)[0] =
        *reinterpret_cast<const uint4*>(h);

    // release PDL dependents (W stores above are visible to them)
    cudaTriggerProgrammaticLaunchCompletion();
}

// ---------------------------------------------------------------------------
// 2) combo (PDL secondary): xconvert blocks [nScB, end) run immediately
//    (disjoint from W); scatter blocks [0, nScB) griddepsync first, then
//    half2-atomic the residual into dequanted W.
// ---------------------------------------------------------------------------
__global__ void combo_kernel(const float* __restrict__ x,
                             const void* __restrict__ vals,
                             const int* __restrict__ rows,
                             const int* __restrict__ cols,
                             const float* __restrict__ alphap, int nnz,
                             int nScB) {
    if ((int)blockIdx.x < nScB) {
        int i = blockIdx.x * blockDim.x + threadIdx.x;
        // wait for dequant's W stores before RMW-ing W
        cudaGridDependencySynchronize();
        if (i >= nnz) return;
        float a = read_alpha(alphap);
        float v;
        if (vals_is_f32(vals)) v = reinterpret_cast<const float*>(vals)[i];
        else v = __half2float(reinterpret_cast<const __half*>(vals)[i]);
        __half hv = __float2half(v * a);
        int col = cols[i];
        __half2 up = (col & 1) ? __halves2half2(__ushort_as_half(0), hv)
                               : __halves2half2(hv, __ushort_as_half(0));
        __half2* dst = reinterpret_cast<__half2*>(
            g_W16 + (size_t)rows[i] * I_FEAT + (col & ~1));
        atomicAdd(dst, up);
    } else {
        // independent of dequant: starts while dequant still runs
        int idx = (blockIdx.x - nScB) * blockDim.x + threadIdx.x;
        if (idx >= M_ROWS * I_FEAT / 8) return;
        const float4* xv = reinterpret_cast<const float4*>(x) + (size_t)idx * 2;
        float4 a = xv[0], b = xv[1];
        __align__(16) __half2 h[4];
        h[0] = __floats2half2_rn(a.x, a.y);
        h[1] = __floats2half2_rn(a.z, a.w);
        h[2] = __floats2half2_rn(b.x, b.y);
        h[3] = __floats2half2_rn(b.z, b.w);
        reinterpret_cast<uint4*>(g_A16)[idx] = *reinterpret_cast<const uint4*>(h);
    }
}

// ---------------------------------------------------------------------------
// GEMM (frozen R7 config): CTA tile 128x128, BK=64, 3-stage cp.async,
// 4 warps (2x2, warp tile 64x64), 2 CTAs/SM, ldmatrix.x4, f32 accum.
// ---------------------------------------------------------------------------
#define BM 128
#define BN 128
#define BK 64
#define STAGES 3
#define KCHUNKS (I_FEAT / BK)              // 64
#define A_BYTES (BM * 128)                 // 16384
#define B_BYTES (BN * 128)                 // 16384
#define STAGE_BYTES (A_BYTES + B_BYTES)    // 32768
#define SMEM_TOTAL (STAGES * STAGE_BYTES)  // 98304
#define NTHREADS 128

__device__ __forceinline__ void ldsm_x4(uint32_t* r, uint32_t addr) {
    asm volatile("ldmatrix.sync.aligned.m8n8.x4.shared.b16 {%0,%1,%2,%3}, [%4];"
                 : "=r"(r[0]), "=r"(r[1]), "=r"(r[2]), "=r"(r[3]) : "r"(addr));
}

__device__ __forceinline__ void mma16816(float* c, const uint32_t* a,
                                         uint32_t b0, uint32_t b1) {
    asm volatile(
        "mma.sync.aligned.m16n8k16.row.col.f32.f16.f16.f32 "
        "{%0,%1,%2,%3}, {%4,%5,%6,%7}, {%8,%9}, {%0,%1,%2,%3};"
        : "+f"(c[0]), "+f"(c[1]), "+f"(c[2]), "+f"(c[3])
        : "r"(a[0]), "r"(a[1]), "r"(a[2]), "r"(a[3]), "r"(b0), "r"(b1));
}

__global__ void __launch_bounds__(NTHREADS, 2)
gemm_kernel(float* __restrict__ out) {
    extern __shared__ char smem[];
    const uint32_t sbase = smem_u32(smem);
    const int tid = threadIdx.x;
    const int wid = tid >> 5;
    const int lid = tid & 31;
    const int bx = blockIdx.x;   // N tile (0..31)
    const int by = blockIdx.y;   // M tile (0..15)

    const int wm = wid >> 1;     // 0..1  (M: 64 rows)
    const int wn = wid & 1;      // 0..1  (N: 64 cols)

    const __half* gA = g_A16 + (size_t)by * BM * I_FEAT;
    const __half* gB = g_W16 + (size_t)bx * BN * I_FEAT;

    const int rlocal = (lid & 7) + ((lid >> 3) & 1) * 8;  // 0..15
    const int csel = lid >> 4;                            // 0/1

    float acc[4][8][4];
#pragma unroll
    for (int a = 0; a < 4; ++a)
#pragma unroll
        for (int b = 0; b < 8; ++b)
#pragma unroll
            for (int r = 0; r < 4; ++r) acc[a][b][r] = 0.0f;

#define LOAD_STAGE(s, ch)                                                      \
    do {                                                                       \
        uint32_t aB_ = sbase + (uint32_t)(s) * STAGE_BYTES;                    \
        uint32_t bB_ = aB_ + A_BYTES;                                          \
        _Pragma("unroll")                                                      \
        for (int i_ = 0; i_ < 8; ++i_) {                                       \
            int id_ = tid + i_ * NTHREADS;                                     \
            int row_ = id_ >> 3, c_ = id_ & 7;                                 \
            uint32_t sw_ = (uint32_t)(c_ ^ (row_ & 7)) << 4;                   \
            uint32_t da_ = aB_ + (uint32_t)row_ * 128u + sw_;                  \
            const __half* sa_ = gA + (size_t)row_ * I_FEAT + (ch) * BK + c_ * 8; \
            asm volatile("cp.async.cg.shared.global [%0], [%1], 16;"          \
                         :: "r"(da_), "l"(sa_) : "memory");                    \
            uint32_t db_ = bB_ + (uint32_t)row_ * 128u + sw_;                  \
            const __half* sb_ = gB + (size_t)row_ * I_FEAT + (ch) * BK + c_ * 8; \
            asm volatile("cp.async.cg.shared.global [%0], [%1], 16;"          \
                         :: "r"(db_), "l"(sb_) : "memory");                    \
        }                                                                      \
        asm volatile("cp.async.commit_group;" ::: "memory");                   \
    } while (0)

    LOAD_STAGE(0, 0);
    LOAD_STAGE(1, 1);

    int s = 0;
    for (int ch = 0; ch < KCHUNKS; ++ch) {
        if (ch == KCHUNKS - 1) {
            asm volatile("cp.async.wait_group 0;" ::: "memory");
        } else {
            asm volatile("cp.async.wait_group 1;" ::: "memory");
        }
        __syncthreads();

        if (ch + 2 < KCHUNKS) {
            int s2 = s + 2;
            if (s2 >= STAGES) s2 -= STAGES;
            LOAD_STAGE(s2, ch + 2);
        }

        const uint32_t aB = sbase + (uint32_t)s * STAGE_BYTES;
        const uint32_t bB = aB + A_BYTES;

#pragma unroll
        for (int ks = 0; ks < 4; ++ks) {
            const int kc = ks * 2 + csel;
            uint32_t rb[4][4];
#pragma unroll
            for (int nt = 0; nt < 4; ++nt) {
                int row = wn * 64 + nt * 16 + rlocal;
                uint32_t addr = bB + (uint32_t)row * 128u +
                                ((uint32_t)(kc ^ (row & 7)) << 4);
                ldsm_x4(rb[nt], addr);
            }
#pragma unroll
            for (int mt = 0; mt < 4; ++mt) {
                int row = wm * 64 + mt * 16 + rlocal;
                uint32_t addr = aB + (uint32_t)row * 128u +
                                ((uint32_t)(kc ^ (row & 7)) << 4);
                uint32_t ra[4];
                ldsm_x4(ra, addr);
#pragma unroll
                for (int nt = 0; nt < 4; ++nt) {
                    mma16816(acc[mt][2 * nt],     ra, rb[nt][0], rb[nt][2]);
                    mma16816(acc[mt][2 * nt + 1], ra, rb[nt][1], rb[nt][3]);
                }
            }
        }

        if (++s == STAGES) s = 0;
    }

    const int r0 = lid >> 2;
    const int c0 = (lid & 3) * 2;
#pragma unroll
    for (int mt = 0; mt < 4; ++mt) {
        int m0 = by * BM + wm * 64 + mt * 16 + r0;
#pragma unroll
        for (int nf = 0; nf < 8; ++nf) {
            int nt = nf >> 1, hi = nf & 1;
            int n0 = bx * BN + wn * 64 + nt * 16 + hi * 8 + c0;
            float2 v0 = make_float2(acc[mt][nf][0], acc[mt][nf][1]);
            float2 v1 = make_float2(acc[mt][nf][2], acc[mt][nf][3]);
            *reinterpret_cast<float2*>(out + (size_t)m0 * O_FEAT + n0) = v0;
            *reinterpret_cast<float2*>(out + (size_t)(m0 + 8) * O_FEAT + n0) = v1;
        }
    }
}

// ---------------------------------------------------------------------------
// kernel_launch — dequant, combo (PDL secondary), gemm
// ---------------------------------------------------------------------------
extern "C" void kernel_launch(void* const* d_in, const int* in_sizes, int n_in,
                              void* d_out, int out_size) {
    const float* x      = (const float*)d_in[0];
    const void*  bp     = d_in[1];
    const float* scales = (const float*)d_in[2];
    const void*  vals   = d_in[3];
    const int*   rows   = (const int*)d_in[4];
    const int*   cols   = (const int*)d_in[5];
    const float* alphap = (n_in > 6) ? (const float*)d_in[6] : nullptr;
    const int nnz = in_sizes[3];

    const int nScB = (nnz + 255) / 256;                  // scatter blocks
    const int nXB  = (M_ROWS * I_FEAT / 8 + 255) / 256;  // xconvert blocks

    dequant_kernel<<<(O_FEAT * I_FEAT / 8) / 256, 256>>>(bp, scales);

    // combo as PDL secondary: xconvert half overlaps dequant's tail
    {
        cudaLaunchConfig_t cfg = {};
        cfg.gridDim = dim3((unsigned)(nScB + nXB), 1, 1);
        cfg.blockDim = dim3(256, 1, 1);
        cfg.dynamicSmemBytes = 0;
        cfg.stream = 0;
        cudaLaunchAttribute attr[1];
        attr[0].id = cudaLaunchAttributeProgrammaticStreamSerialization;
        attr[0].val.programmaticStreamSerializationAllowed = 1;
        cfg.attrs = attr;
        cfg.numAttrs = 1;
        cudaLaunchKernelEx(&cfg, combo_kernel, x, vals, rows, cols, alphap,
                           nnz, nScB);
    }

    cudaFuncSetAttribute(gemm_kernel,
                         cudaFuncAttributeMaxDynamicSharedMemorySize, SMEM_TOTAL);
    gemm_kernel<<<dim3(O_FEAT / BN, M_ROWS / BM, 1), NTHREADS, SMEM_TOTAL>>>(
        (float*)d_out);
}